// round 16
// baseline (speedup 1.0000x reference)
#include <cuda_runtime.h>
#include <cuda_fp16.h>
#include <mma.h>
#include <math.h>

using namespace nvcuda;

#define NN 50000
#define EE 800000
#define DD 64
#define EDD 16
#define LL 4
#define GG 64
#define NB 196   // scan blocks of 256 nodes

// ---------------- f32x2 packed helpers (sm_100a) ---------------------------
__device__ __forceinline__ unsigned long long pk2(float x, float y) {
    unsigned long long r;
    asm("mov.b64 %0, {%1,%2};" : "=l"(r) : "f"(x), "f"(y));
    return r;
}
__device__ __forceinline__ float2 upk2(unsigned long long v) {
    float2 r;
    asm("mov.b64 {%0,%1}, %2;" : "=f"(r.x), "=f"(r.y) : "l"(v));
    return r;
}
__device__ __forceinline__ unsigned long long ffma2(
    unsigned long long a, unsigned long long b, unsigned long long c) {
    unsigned long long d;
    asm("fma.rn.f32x2 %0, %1, %2, %3;" : "=l"(d) : "l"(a), "l"(b), "l"(c));
    return d;
}

// ---------------- scratch (static device globals; no runtime alloc) --------
// g_cnt and g_dhist are SELF-CLEANING: zero-initialized at module load, and
// every execution re-zeroes them (degorder / scanC) after consumption, so
// k_count and k_scanA can run without a preparatory zeroing pass.
__device__ __half2 g_hwh[2][NN * 32];     // double-buffered h @ W (fp16)
__device__ float  g_ssrc2[2][NN];         // double-buffered hw . a_src
__device__ float  g_sdst2[2][NN];         // double-buffered hw . a_dst
__device__ float  g_hbuf[NN * DD];        // final-layer node features (pool)
__device__ uint4  g_edge[EE];             // {src, el01(fp16x2), el23(fp16x2), pad}
__device__ float  g_wev[LL * EDD];        // per-layer We @ a_e
__device__ int    g_rowptr[NN + 1];       // CSR row pointers (by dst)
__device__ int    g_cnt[NN];              // degrees (self-cleaning)
__device__ int    g_epos[EE];             // edge rank within its dst row
__device__ int    g_gstart[GG + 1];       // group boundaries in sorted batch
__device__ float  g_pooled[GG * DD];
__device__ int    g_bsum[NB];             // scan phase A partials
__device__ int    g_dhist[64];            // degree histogram (self-cleaning)
__device__ int    g_dcur[64];             // degree bucket cursors
__device__ int    g_nodeord[NN];          // nodes, degree-DESCENDING order

// ---------------- wev + group boundaries (no counter zeroing needed) -------
__global__ void k_prep(const float* __restrict__ We,
                       const float* __restrict__ a_e,
                       const int* __restrict__ batch) {
    int i = blockIdx.x * blockDim.x + threadIdx.x;
    if (blockIdx.x == 0 && threadIdx.x < LL * EDD) {
        int l = threadIdx.x >> 4, jj = threadIdx.x & 15;
        float s = 0.f;
        const float* wr = We + (l * EDD + jj) * DD;
        const float* ar = a_e + l * DD;
#pragma unroll 8
        for (int k = 0; k < DD; k++) s += wr[k] * ar[k];
        g_wev[threadIdx.x] = s;
    }
    if (i < NN) {
        int cur = batch[i];
        if (i == 0) {
            for (int g = 0; g <= cur; g++) g_gstart[g] = 0;
        } else {
            int prev = batch[i - 1];
            for (int g = prev + 1; g <= cur; g++) g_gstart[g] = i;
        }
        if (i == NN - 1) {
            for (int g = cur + 1; g <= GG; g++) g_gstart[g] = NN;
        }
    }
}

// count + record each edge's rank within its dst row
__global__ void k_count(const int* __restrict__ ei) {
    int e = blockIdx.x * blockDim.x + threadIdx.x;
    if (e < EE) g_epos[e] = atomicAdd(&g_cnt[ei[EE + e]], 1);
}

// scan phase A: per-256-node block sums + fused degree histogram
__global__ void k_scanA() {
    __shared__ int red[256];
    __shared__ int hist[64];
    int blk = blockIdx.x, t = threadIdx.x;
    if (t < 64) hist[t] = 0;
    __syncthreads();
    int idx = blk * 256 + t;
    int c = (idx < NN) ? g_cnt[idx] : 0;
    if (idx < NN) atomicAdd(&hist[min(c, 63)], 1);
    red[t] = c;
    __syncthreads();
    for (int off = 128; off; off >>= 1) {
        if (t < off) red[t] += red[t + off];
        __syncthreads();
    }
    if (t == 0) g_bsum[blk] = red[0];
    if (t < 64 && hist[t]) atomicAdd(&g_dhist[t], hist[t]);
}

// scan phase C: warp-shuffle scans. Block offset = masked warp-REDUCTION of
// g_bsum (not a scan). Block 0 also builds g_dcur and self-cleans g_dhist.
__global__ void k_scanC() {
    __shared__ int wsum[8];   // per-warp inclusive totals of node counts
    __shared__ int bpart[8];  // per-warp partials of the block offset
    __shared__ int woff[8];
    __shared__ int boff;
    int blk = blockIdx.x, t = threadIdx.x;
    int w = t >> 5, lane = t & 31;
    int idx = blk * 256 + t;
    int c = (idx < NN) ? g_cnt[idx] : 0;

    int part = (t < blk) ? g_bsum[t] : 0;   // blk <= 195 < 256
#pragma unroll
    for (int off = 16; off; off >>= 1)
        part += __shfl_xor_sync(0xffffffffu, part, off);
    if (lane == 0) bpart[w] = part;

    int sc = c;
#pragma unroll
    for (int off = 1; off < 32; off <<= 1) {
        int v = __shfl_up_sync(0xffffffffu, sc, off);
        if (lane >= off) sc += v;
    }
    if (lane == 31) wsum[w] = sc;
    __syncthreads();
    if (t == 0) {
        int run = 0, bo = 0;
#pragma unroll
        for (int i = 0; i < 8; i++) {
            woff[i] = run; run += wsum[i]; bo += bpart[i];
        }
        boff = bo;
    }
    if (blk == 0 && t == 32) {   // degree-hist scan + self-clean
        int run = 0;
        for (int i = 0; i < 64; i++) {
            int h = g_dhist[i]; g_dcur[i] = run; run += h; g_dhist[i] = 0;
        }
    }
    __syncthreads();
    if (idx < NN) g_rowptr[idx] = boff + woff[w] + sc - c;   // exclusive
    if (blk == 0 && t == 0) g_rowptr[NN] = EE;
}

// degree-ordered permutation, DESCENDING degree; self-cleans g_cnt
__global__ void k_degorder() {
    int i = blockIdx.x * blockDim.x + threadIdx.x;
    if (i >= NN) return;
    int deg = min(g_cnt[i], 63);
    g_cnt[i] = 0;                          // restore zero for next replay
    int pos = atomicAdd(&g_dcur[deg], 1);
    g_nodeord[NN - 1 - pos] = i;
}

// ---------------- scatter: AoS edge {src, el fp16x4} (one 16B write) -------
__global__ void k_scatter(const int* __restrict__ ei,
                          const float* __restrict__ ea) {
    __shared__ float wv[LL * EDD];
    if (threadIdx.x < LL * EDD) wv[threadIdx.x] = g_wev[threadIdx.x];
    __syncthreads();
    int e = blockIdx.x * blockDim.x + threadIdx.x;
    if (e >= EE) return;
    int s = ei[e], d = ei[EE + e];
    int pos = g_rowptr[d] + g_epos[e];
    const float4* p = (const float4*)(ea + (size_t)e * EDD);
    float4 v0 = p[0], v1 = p[1], v2 = p[2], v3 = p[3];
    float el[LL];
#pragma unroll
    for (int l = 0; l < LL; l++) {
        const float* w = wv + l * EDD;
        el[l] = v0.x * w[0]  + v0.y * w[1]  + v0.z * w[2]  + v0.w * w[3]
              + v1.x * w[4]  + v1.y * w[5]  + v1.z * w[6]  + v1.w * w[7]
              + v2.x * w[8]  + v2.y * w[9]  + v2.z * w[10] + v2.w * w[11]
              + v3.x * w[12] + v3.y * w[13] + v3.z * w[14] + v3.w * w[15];
    }
    __half2 e01 = __floats2half2_rn(el[0], el[1]);
    __half2 e23 = __floats2half2_rn(el[2], el[3]);
    uint4 u;
    u.x = (unsigned)s;
    u.y = *(unsigned*)&e01;
    u.z = *(unsigned*)&e23;
    u.w = 0;
    g_edge[pos] = u;
}

// ---------------- layer-0 gemm: hw0 = x @ W0 (fp16 wmma, fp16 hw out) -------
__global__ void __launch_bounds__(256, 4)
k_gemm0(const float* __restrict__ x,
        const float* __restrict__ W_l,
        const float* __restrict__ as_l,
        const float* __restrict__ ad_l) {
    __shared__ __align__(32) __half shA[64 * 72];
    __shared__ __align__(32) __half shB[64 * 72];
    __shared__ float sout[64 * 72];
    __shared__ float sas[64], sad[64];
    int t = threadIdx.x;
    int row0 = blockIdx.x * 64;
    if (t < 64) { sas[t] = as_l[t]; sad[t] = ad_l[t]; }
    for (int i = t; i < 1024; i += 256) {
        int r = i >> 4, ck = i & 15;
        float4 wv = ((const float4*)W_l)[i];
        *(__half2*)&shB[r * 72 + ck * 4]     = __floats2half2_rn(wv.x, wv.y);
        *(__half2*)&shB[r * 72 + ck * 4 + 2] = __floats2half2_rn(wv.z, wv.w);
        int row = row0 + r;
        float4 v = (row < NN) ? ((const float4*)x)[row * 16 + ck]
                              : make_float4(0.f, 0.f, 0.f, 0.f);
        *(__half2*)&shA[r * 72 + ck * 4]     = __floats2half2_rn(v.x, v.y);
        *(__half2*)&shA[r * 72 + ck * 4 + 2] = __floats2half2_rn(v.z, v.w);
    }
    __syncthreads();

    int w = t >> 5;
    int trow = w >> 2, tcol = w & 3;
    wmma::fragment<wmma::accumulator, 16, 16, 16, float> acc0, acc1;
    wmma::fill_fragment(acc0, 0.f);
    wmma::fill_fragment(acc1, 0.f);
#pragma unroll
    for (int kk = 0; kk < 4; kk++) {
        wmma::fragment<wmma::matrix_a, 16, 16, 16, __half, wmma::row_major> a0, a1;
        wmma::fragment<wmma::matrix_b, 16, 16, 16, __half, wmma::row_major> bf;
        wmma::load_matrix_sync(bf, &shB[kk * 16 * 72 + tcol * 16], 72);
        wmma::load_matrix_sync(a0, &shA[trow * 16 * 72 + kk * 16], 72);
        wmma::load_matrix_sync(a1, &shA[(trow + 2) * 16 * 72 + kk * 16], 72);
        wmma::mma_sync(acc0, a0, bf, acc0);
        wmma::mma_sync(acc1, a1, bf, acc1);
    }
    wmma::store_matrix_sync(&sout[trow * 16 * 72 + tcol * 16], acc0, 72,
                            wmma::mem_row_major);
    wmma::store_matrix_sync(&sout[(trow + 2) * 16 * 72 + tcol * 16], acc1, 72,
                            wmma::mem_row_major);
    __syncthreads();

    int r = t >> 2, q = t & 3;          // cols q*16..q*16+15
    int row = row0 + r;
    float4 v[4];
    float ps = 0.f, pd = 0.f;
#pragma unroll
    for (int i = 0; i < 4; i++) {
        v[i] = *(const float4*)&sout[r * 72 + q * 16 + i * 4];
        int c = q * 16 + i * 4;
        ps += v[i].x * sas[c]     + v[i].y * sas[c + 1]
            + v[i].z * sas[c + 2] + v[i].w * sas[c + 3];
        pd += v[i].x * sad[c]     + v[i].y * sad[c + 1]
            + v[i].z * sad[c + 2] + v[i].w * sad[c + 3];
    }
    ps += __shfl_xor_sync(0xffffffffu, ps, 1);
    ps += __shfl_xor_sync(0xffffffffu, ps, 2);
    pd += __shfl_xor_sync(0xffffffffu, pd, 1);
    pd += __shfl_xor_sync(0xffffffffu, pd, 2);
    if (row < NN) {
        __half2 h0 = __floats2half2_rn(v[0].x, v[0].y);
        __half2 h1 = __floats2half2_rn(v[0].z, v[0].w);
        __half2 h2 = __floats2half2_rn(v[1].x, v[1].y);
        __half2 h3 = __floats2half2_rn(v[1].z, v[1].w);
        __half2 h4 = __floats2half2_rn(v[2].x, v[2].y);
        __half2 h5 = __floats2half2_rn(v[2].z, v[2].w);
        __half2 h6 = __floats2half2_rn(v[3].x, v[3].y);
        __half2 h7 = __floats2half2_rn(v[3].z, v[3].w);
        uint4 u0, u1;
        u0.x = *(unsigned*)&h0; u0.y = *(unsigned*)&h1;
        u0.z = *(unsigned*)&h2; u0.w = *(unsigned*)&h3;
        u1.x = *(unsigned*)&h4; u1.y = *(unsigned*)&h5;
        u1.z = *(unsigned*)&h6; u1.w = *(unsigned*)&h7;
        ((uint4*)g_hwh[0])[row * 8 + q * 2]     = u0;
        ((uint4*)g_hwh[0])[row * 8 + q * 2 + 1] = u1;
        if (q == 0) { g_ssrc2[0][row] = ps; g_sdst2[0][row] = pd; }
    }
}

// ---------------- FUSED: agg(layer l) + gemm(layer l+1) --------------------
__global__ void __launch_bounds__(512, 3)
k_fused(int layer,
        const float* __restrict__ Wn,    // W[l+1]
        const float* __restrict__ asn,   // a_src[l+1]
        const float* __restrict__ adn,   // a_dst[l+1]
        const float* __restrict__ b_l) { // b[l]
    __shared__ __align__(32) __half shA[64 * 72];
    __shared__ __align__(32) __half shB[64 * 72];
    __shared__ float sout[64 * 72];
    __shared__ float sas[64], sad[64];
    __shared__ int rowids[64];
    int rd = layer & 1, wr = (layer + 1) & 1;
    const float* ssrc_in = g_ssrc2[rd];
    const float* sdst_in = g_sdst2[rd];
    const float4* hw_in = (const float4*)g_hwh[rd];   // 8 float4 per row
    int shift = 16 * layer;
    int t = threadIdx.x;
    int w = t >> 5, lane = t & 31;
    int grp = lane >> 3, hl = lane & 7;
    int local = w * 4 + grp;
    int oi = blockIdx.x * 64 + local;
    int n = (oi < NN) ? g_nodeord[oi] : -1;
    if (t < 64) { sas[t] = asn[t]; sad[t] = adn[t]; }
    if (hl == 0) rowids[local] = n;
    for (int i = t; i < 1024; i += 512) {
        int r = i >> 4, ck = i & 15;
        float4 wv = ((const float4*)Wn)[i];
        *(__half2*)&shB[r * 72 + ck * 4]     = __floats2half2_rn(wv.x, wv.y);
        *(__half2*)&shB[r * 72 + ck * 4 + 2] = __floats2half2_rn(wv.z, wv.w);
    }

    // ---- agg phase: lane covers cols 8hl..8hl+7 ----
    if (n >= 0) {
        int s0 = g_rowptr[n], s1 = g_rowptr[n + 1];
        float sd = sdst_in[n];
        unsigned long long acc0 = pk2(0.f, 0.f);
        unsigned long long acc1 = pk2(0.f, 0.f);
        unsigned long long acc2 = pk2(0.f, 0.f);
        unsigned long long acc3 = pk2(0.f, 0.f);
        float denom = 0.f;
#pragma unroll 4
        for (int i = s0; i < s1; i++) {
            uint4 u = g_edge[i];
            int src = (int)u.x;
            unsigned long long pk = ((unsigned long long)u.z << 32) | u.y;
            unsigned short hb = (unsigned short)(pk >> shift);
            float elv = __half2float(__ushort_as_half(hb));
            float sc = ssrc_in[src] + sd + elv;
            sc = fmaxf(sc, 0.2f * sc);           // leaky_relu
            float p = __expf(sc);
            denom += p;
            float4 va = hw_in[src * 8 + hl];     // 128B row, one LDG.128
            const __half2* hp = (const __half2*)&va;
            float2 f0 = __half22float2(hp[0]);
            float2 f1 = __half22float2(hp[1]);
            float2 f2 = __half22float2(hp[2]);
            float2 f3 = __half22float2(hp[3]);
            unsigned long long pp = pk2(p, p);
            acc0 = ffma2(pp, pk2(f0.x, f0.y), acc0);
            acc1 = ffma2(pp, pk2(f1.x, f1.y), acc1);
            acc2 = ffma2(pp, pk2(f2.x, f2.y), acc2);
            acc3 = ffma2(pp, pk2(f3.x, f3.y), acc3);
        }
        float inv = (denom > 0.f) ? (1.f / denom) : 0.f;
        float2 a0 = upk2(acc0), a1 = upk2(acc1), a2 = upk2(acc2), a3 = upk2(acc3);
        float4 ba = ((const float4*)b_l)[2 * hl];
        float4 bb = ((const float4*)b_l)[2 * hl + 1];
        float o0 = fmaxf(a0.x * inv + ba.x, 0.f);
        float o1 = fmaxf(a0.y * inv + ba.y, 0.f);
        float o2 = fmaxf(a1.x * inv + ba.z, 0.f);
        float o3 = fmaxf(a1.y * inv + ba.w, 0.f);
        float o4 = fmaxf(a2.x * inv + bb.x, 0.f);
        float o5 = fmaxf(a2.y * inv + bb.y, 0.f);
        float o6 = fmaxf(a3.x * inv + bb.z, 0.f);
        float o7 = fmaxf(a3.y * inv + bb.w, 0.f);
        *(__half2*)&shA[local * 72 + 8 * hl]     = __floats2half2_rn(o0, o1);
        *(__half2*)&shA[local * 72 + 8 * hl + 2] = __floats2half2_rn(o2, o3);
        *(__half2*)&shA[local * 72 + 8 * hl + 4] = __floats2half2_rn(o4, o5);
        *(__half2*)&shA[local * 72 + 8 * hl + 6] = __floats2half2_rn(o6, o7);
    } else {
        __half2 z = __floats2half2_rn(0.f, 0.f);
        *(__half2*)&shA[local * 72 + 8 * hl]     = z;
        *(__half2*)&shA[local * 72 + 8 * hl + 2] = z;
        *(__half2*)&shA[local * 72 + 8 * hl + 4] = z;
        *(__half2*)&shA[local * 72 + 8 * hl + 6] = z;
    }
    __syncthreads();

    // ---- gemm phase ----
    {
        int trow = w >> 2, tcol = w & 3;
        wmma::fragment<wmma::accumulator, 16, 16, 16, float> acc;
        wmma::fill_fragment(acc, 0.f);
#pragma unroll
        for (int kk = 0; kk < 4; kk++) {
            wmma::fragment<wmma::matrix_a, 16, 16, 16, __half, wmma::row_major> af;
            wmma::fragment<wmma::matrix_b, 16, 16, 16, __half, wmma::row_major> bf;
            wmma::load_matrix_sync(af, &shA[trow * 16 * 72 + kk * 16], 72);
            wmma::load_matrix_sync(bf, &shB[kk * 16 * 72 + tcol * 16], 72);
            wmma::mma_sync(acc, af, bf, acc);
        }
        wmma::store_matrix_sync(&sout[trow * 16 * 72 + tcol * 16], acc, 72,
                                wmma::mem_row_major);
    }
    __syncthreads();

    // ---- epilogue ----
    int r = t >> 3, q = t & 7;
    float4 v0 = *(const float4*)&sout[r * 72 + q * 8];
    float4 v1 = *(const float4*)&sout[r * 72 + q * 8 + 4];
    int c = q * 8;
    float ps = v0.x * sas[c]     + v0.y * sas[c + 1]
             + v0.z * sas[c + 2] + v0.w * sas[c + 3]
             + v1.x * sas[c + 4] + v1.y * sas[c + 5]
             + v1.z * sas[c + 6] + v1.w * sas[c + 7];
    float pd = v0.x * sad[c]     + v0.y * sad[c + 1]
             + v0.z * sad[c + 2] + v0.w * sad[c + 3]
             + v1.x * sad[c + 4] + v1.y * sad[c + 5]
             + v1.z * sad[c + 6] + v1.w * sad[c + 7];
    ps += __shfl_xor_sync(0xffffffffu, ps, 1);
    ps += __shfl_xor_sync(0xffffffffu, ps, 2);
    ps += __shfl_xor_sync(0xffffffffu, ps, 4);
    pd += __shfl_xor_sync(0xffffffffu, pd, 1);
    pd += __shfl_xor_sync(0xffffffffu, pd, 2);
    pd += __shfl_xor_sync(0xffffffffu, pd, 4);
    int rowg = rowids[r];
    if (rowg >= 0) {
        __half2 h0 = __floats2half2_rn(v0.x, v0.y);
        __half2 h1 = __floats2half2_rn(v0.z, v0.w);
        __half2 h2 = __floats2half2_rn(v1.x, v1.y);
        __half2 h3 = __floats2half2_rn(v1.z, v1.w);
        uint4 u;
        u.x = *(unsigned*)&h0; u.y = *(unsigned*)&h1;
        u.z = *(unsigned*)&h2; u.w = *(unsigned*)&h3;
        ((uint4*)g_hwh[wr])[rowg * 8 + q] = u;
        if (q == 0) { g_ssrc2[wr][rowg] = ps; g_sdst2[wr][rowg] = pd; }
    }
}

// ---------------- final-layer aggregation (layer 3, reads parity 1) --------
__global__ void k_agg_last(const float* __restrict__ b_l) {
    int warp = (blockIdx.x * blockDim.x + threadIdx.x) >> 5;
    int lane = threadIdx.x & 31;
    int grp = lane >> 3, hl = lane & 7;
    int oi = warp * 4 + grp;
    if (oi >= NN) return;
    int n = g_nodeord[oi];
    int s0 = g_rowptr[n], s1 = g_rowptr[n + 1];
    float sd = g_sdst2[1][n];
    const float4* hw_in = (const float4*)g_hwh[1];
    unsigned long long acc0 = pk2(0.f, 0.f);
    unsigned long long acc1 = pk2(0.f, 0.f);
    unsigned long long acc2 = pk2(0.f, 0.f);
    unsigned long long acc3 = pk2(0.f, 0.f);
    float denom = 0.f;
#pragma unroll 4
    for (int i = s0; i < s1; i++) {
        uint4 u = g_edge[i];
        int src = (int)u.x;
        float elv = __half2float(__ushort_as_half((unsigned short)(u.z >> 16)));
        float sc = g_ssrc2[1][src] + sd + elv;
        sc = fmaxf(sc, 0.2f * sc);
        float p = __expf(sc);
        denom += p;
        float4 va = hw_in[src * 8 + hl];
        const __half2* hp = (const __half2*)&va;
        float2 f0 = __half22float2(hp[0]);
        float2 f1 = __half22float2(hp[1]);
        float2 f2 = __half22float2(hp[2]);
        float2 f3 = __half22float2(hp[3]);
        unsigned long long pp = pk2(p, p);
        acc0 = ffma2(pp, pk2(f0.x, f0.y), acc0);
        acc1 = ffma2(pp, pk2(f1.x, f1.y), acc1);
        acc2 = ffma2(pp, pk2(f2.x, f2.y), acc2);
        acc3 = ffma2(pp, pk2(f3.x, f3.y), acc3);
    }
    float inv = (denom > 0.f) ? (1.f / denom) : 0.f;
    float2 a0 = upk2(acc0), a1 = upk2(acc1), a2 = upk2(acc2), a3 = upk2(acc3);
    float4 ba = ((const float4*)b_l)[2 * hl];
    float4 bb = ((const float4*)b_l)[2 * hl + 1];
    float4 oa = make_float4(a0.x * inv + ba.x, a0.y * inv + ba.y,
                            a1.x * inv + ba.z, a1.y * inv + ba.w);
    float4 ob = make_float4(a2.x * inv + bb.x, a2.y * inv + bb.y,
                            a3.x * inv + bb.z, a3.y * inv + bb.w);
    float4* hout = (float4*)g_hbuf;
    hout[n * 16 + 2 * hl] = oa;
    hout[n * 16 + 2 * hl + 1] = ob;
}

// ---------------- global mean pool (block per group) ------------------------
__global__ void k_pool() {
    const float* h = g_hbuf;
    int g = blockIdx.x;
    int t = threadIdx.x;
    int col = t & 63, rs = t >> 6;
    int s0 = g_gstart[g], s1 = g_gstart[g + 1];
    float acc = 0.f;
    for (int n = s0 + rs; n < s1; n += 4) acc += h[n * DD + col];
    __shared__ float sh[256];
    sh[t] = acc;
    __syncthreads();
    if (rs == 0) {
        float v = sh[col] + sh[64 + col] + sh[128 + col] + sh[192 + col];
        float cnt = (float)(s1 - s0);
        g_pooled[g * DD + col] = v / fmaxf(cnt, 1.f);
    }
}

// ---------------- FC: out[g, 2k2..2k2+1] = pooled[g] . Wfc + bfc -----------
__global__ void k_fc(const float* __restrict__ Wfc,
                     const float* __restrict__ bfc,
                     float* __restrict__ out) {
    int g = blockIdx.y;
    int k2 = blockIdx.x * 256 + threadIdx.x;   // pair index 0..1023
    __shared__ float sp[DD];
    if (threadIdx.x < DD) sp[threadIdx.x] = g_pooled[g * DD + threadIdx.x];
    __syncthreads();
    const float2* W2 = (const float2*)Wfc;
    float2 bb = ((const float2*)bfc)[k2];
    unsigned long long acc = pk2(bb.x, bb.y);
#pragma unroll
    for (int d = 0; d < DD; d++) {
        float2 w = __ldg(&W2[d * 1024 + k2]);
        acc = ffma2(pk2(sp[d], sp[d]), pk2(w.x, w.y), acc);
    }
    ((float2*)out)[g * 1024 + k2] = upk2(acc);
}

// ---------------- launch -----------------------------------------------------
// Graph-forked: CSR build starts at t=0 on s2 (self-cleaning counters remove
// the prep dependency); main stream runs prep + gemm0 concurrently. Scatter
// waits on prep (needs g_wev). Streams/events created per call, not destroyed.
extern "C" void kernel_launch(void* const* d_in, const int* in_sizes, int n_in,
                              void* d_out, int out_size) {
    const float* x     = (const float*)d_in[0];
    const int*   ei    = (const int*)  d_in[1];
    const float* ea    = (const float*)d_in[2];
    const int*   batch = (const int*)  d_in[3];
    const float* W     = (const float*)d_in[4];
    const float* a_src = (const float*)d_in[5];
    const float* a_dst = (const float*)d_in[6];
    const float* We    = (const float*)d_in[7];
    const float* a_e   = (const float*)d_in[8];
    const float* b     = (const float*)d_in[9];
    const float* Wfc   = (const float*)d_in[10];
    const float* bfc   = (const float*)d_in[11];
    float* out = (float*)d_out;

    cudaStream_t s2;
    cudaStreamCreateWithFlags(&s2, cudaStreamNonBlocking);
    cudaEvent_t evFork, evPrep, evJoin;
    cudaEventCreateWithFlags(&evFork, cudaEventDisableTiming);
    cudaEventCreateWithFlags(&evPrep, cudaEventDisableTiming);
    cudaEventCreateWithFlags(&evJoin, cudaEventDisableTiming);

    // fork at t=0: CSR chain on s2, prep+gemm0 on main
    cudaEventRecord(evFork, 0);
    cudaStreamWaitEvent(s2, evFork, 0);
    k_count<<<(EE + 255) / 256, 256, 0, s2>>>(ei);
    k_scanA<<<NB, 256, 0, s2>>>();
    k_scanC<<<NB, 256, 0, s2>>>();
    k_degorder<<<(NN + 255) / 256, 256, 0, s2>>>();

    k_prep<<<(NN + 255) / 256, 256>>>(We, a_e, batch);
    cudaEventRecord(evPrep, 0);
    k_gemm0<<<(NN + 63) / 64, 256>>>(x, W, a_src, a_dst);

    cudaStreamWaitEvent(s2, evPrep, 0);   // scatter needs g_wev
    k_scatter<<<(EE + 255) / 256, 256, 0, s2>>>(ei, ea);
    cudaEventRecord(evJoin, s2);

    cudaStreamWaitEvent(0, evJoin, 0);

    // fused agg(l) + gemm(l+1), l = 0..2
    for (int l = 0; l < LL - 1; l++) {
        k_fused<<<(NN + 63) / 64, 512>>>(l, W + (l + 1) * DD * DD,
                                         a_src + (l + 1) * DD,
                                         a_dst + (l + 1) * DD,
                                         b + l * DD);
    }
    // final aggregation (layer 3)
    k_agg_last<<<(NN * 8 + 255) / 256, 256>>>(b + 3 * DD);

    k_pool<<<GG, 256>>>();
    dim3 fcg(1024 / 256, GG);
    k_fc<<<fcg, 256>>>(Wfc, bfc, out);
}

// round 17
// speedup vs baseline: 1.0749x; 1.0749x over previous
#include <cuda_runtime.h>
#include <cuda_fp16.h>
#include <mma.h>
#include <math.h>

using namespace nvcuda;

#define NN 50000
#define EE 800000
#define DD 64
#define EDD 16
#define LL 4
#define GG 64
#define NB 196   // scan blocks of 256 nodes

// ---------------- f32x2 packed helpers (sm_100a) ---------------------------
__device__ __forceinline__ unsigned long long pk2(float x, float y) {
    unsigned long long r;
    asm("mov.b64 %0, {%1,%2};" : "=l"(r) : "f"(x), "f"(y));
    return r;
}
__device__ __forceinline__ float2 upk2(unsigned long long v) {
    float2 r;
    asm("mov.b64 {%0,%1}, %2;" : "=f"(r.x), "=f"(r.y) : "l"(v));
    return r;
}
__device__ __forceinline__ unsigned long long ffma2(
    unsigned long long a, unsigned long long b, unsigned long long c) {
    unsigned long long d;
    asm("fma.rn.f32x2 %0, %1, %2, %3;" : "=l"(d) : "l"(a), "l"(b), "l"(c));
    return d;
}

// ---------------- scratch (static device globals; no runtime alloc) --------
// g_cnt and g_dhist are SELF-CLEANING: zero-initialized at module load, and
// every execution re-zeroes them after consumption, so k_count / k_scanA can
// start at t=0 with no preparatory zeroing pass.
__device__ __half2 g_hwh[2][NN * 32];     // double-buffered h @ W (fp16)
__device__ float  g_ssrc2[2][NN];         // double-buffered hw . a_src
__device__ float  g_sdst2[2][NN];         // double-buffered hw . a_dst
__device__ float  g_hbuf[NN * DD];        // final-layer node features (pool)
__device__ uint4  g_edge[EE];             // {src, el01(fp16x2), el23(fp16x2), pad}
__device__ float  g_wev[LL * EDD];        // per-layer We @ a_e
__device__ int    g_rowptr[NN + 1];       // CSR row pointers (by dst)
__device__ int    g_cnt[NN];              // degrees (self-cleaning)
__device__ int    g_epos[EE];             // edge rank within its dst row
__device__ int    g_gstart[GG + 1];       // group boundaries in sorted batch
__device__ float  g_pooled[GG * DD];
__device__ int    g_bsum[NB];             // scan phase A partials
__device__ int    g_dhist[64];            // degree histogram (self-cleaning)
__device__ int    g_dcur[64];             // degree bucket cursors
__device__ int    g_nodeord[NN];          // nodes, degree-DESCENDING order

// ---------------- wev + group boundaries ------------------------------------
__global__ void k_prep(const float* __restrict__ We,
                       const float* __restrict__ a_e,
                       const int* __restrict__ batch) {
    int i = blockIdx.x * blockDim.x + threadIdx.x;
    if (blockIdx.x == 0 && threadIdx.x < LL * EDD) {
        int l = threadIdx.x >> 4, jj = threadIdx.x & 15;
        float s = 0.f;
        const float* wr = We + (l * EDD + jj) * DD;
        const float* ar = a_e + l * DD;
#pragma unroll 8
        for (int k = 0; k < DD; k++) s += wr[k] * ar[k];
        g_wev[threadIdx.x] = s;
    }
    if (i < NN) {
        int cur = batch[i];
        if (i == 0) {
            for (int g = 0; g <= cur; g++) g_gstart[g] = 0;
        } else {
            int prev = batch[i - 1];
            for (int g = prev + 1; g <= cur; g++) g_gstart[g] = i;
        }
        if (i == NN - 1) {
            for (int g = cur + 1; g <= GG; g++) g_gstart[g] = NN;
        }
    }
}

// count + record each edge's rank within its dst row
__global__ void k_count(const int* __restrict__ ei) {
    int e = blockIdx.x * blockDim.x + threadIdx.x;
    if (e < EE) g_epos[e] = atomicAdd(&g_cnt[ei[EE + e]], 1);
}

// scan phase A: per-256-node block sums + fused degree histogram
__global__ void k_scanA() {
    __shared__ int red[256];
    __shared__ int hist[64];
    int blk = blockIdx.x, t = threadIdx.x;
    if (t < 64) hist[t] = 0;
    __syncthreads();
    int idx = blk * 256 + t;
    int c = (idx < NN) ? g_cnt[idx] : 0;
    if (idx < NN) atomicAdd(&hist[min(c, 63)], 1);
    red[t] = c;
    __syncthreads();
    for (int off = 128; off; off >>= 1) {
        if (t < off) red[t] += red[t + off];
        __syncthreads();
    }
    if (t == 0) g_bsum[blk] = red[0];
    if (t < 64 && hist[t]) atomicAdd(&g_dhist[t], hist[t]);
}

// scan phase C: warp-shuffle scans. Block offset = masked warp-REDUCTION of
// g_bsum. Block 0 also builds g_dcur and self-cleans g_dhist.
__global__ void k_scanC() {
    __shared__ int wsum[8];
    __shared__ int bpart[8];
    __shared__ int woff[8];
    __shared__ int boff;
    int blk = blockIdx.x, t = threadIdx.x;
    int w = t >> 5, lane = t & 31;
    int idx = blk * 256 + t;
    int c = (idx < NN) ? g_cnt[idx] : 0;

    int part = (t < blk) ? g_bsum[t] : 0;   // blk <= 195 < 256
#pragma unroll
    for (int off = 16; off; off >>= 1)
        part += __shfl_xor_sync(0xffffffffu, part, off);
    if (lane == 0) bpart[w] = part;

    int sc = c;
#pragma unroll
    for (int off = 1; off < 32; off <<= 1) {
        int v = __shfl_up_sync(0xffffffffu, sc, off);
        if (lane >= off) sc += v;
    }
    if (lane == 31) wsum[w] = sc;
    __syncthreads();
    if (t == 0) {
        int run = 0, bo = 0;
#pragma unroll
        for (int i = 0; i < 8; i++) {
            woff[i] = run; run += wsum[i]; bo += bpart[i];
        }
        boff = bo;
    }
    if (blk == 0 && t == 32) {   // degree-hist scan + self-clean
        int run = 0;
        for (int i = 0; i < 64; i++) {
            int h = g_dhist[i]; g_dcur[i] = run; run += h; g_dhist[i] = 0;
        }
    }
    __syncthreads();
    if (idx < NN) g_rowptr[idx] = boff + woff[w] + sc - c;   // exclusive
    if (blk == 0 && t == 0) g_rowptr[NN] = EE;
}

// degree-ordered permutation, DESCENDING degree; self-cleans g_cnt.
// Hierarchical: block-local smem histogram -> ONE global atomic per bucket
// per block (64 vs 256; hot-bucket contention 5000 -> 196 serialized ops).
__global__ void k_degorder() {
    __shared__ int hist[64];
    __shared__ int base[64];
    int t = threadIdx.x;
    int i = blockIdx.x * 256 + t;
    if (t < 64) hist[t] = 0;
    __syncthreads();
    int deg = 0, lrank = 0;
    if (i < NN) {
        deg = min(g_cnt[i], 63);
        g_cnt[i] = 0;                      // restore zero for next replay
        lrank = atomicAdd(&hist[deg], 1);  // rank within block for this bucket
    }
    __syncthreads();
    if (t < 64 && hist[t]) base[t] = atomicAdd(&g_dcur[t], hist[t]);
    __syncthreads();
    if (i < NN) {
        int pos = base[deg] + lrank;
        g_nodeord[NN - 1 - pos] = i;
    }
}

// ---------------- scatter: AoS edge {src, el fp16x4} (one 16B write) -------
__global__ void k_scatter(const int* __restrict__ ei,
                          const float* __restrict__ ea) {
    __shared__ float wv[LL * EDD];
    if (threadIdx.x < LL * EDD) wv[threadIdx.x] = g_wev[threadIdx.x];
    __syncthreads();
    int e = blockIdx.x * blockDim.x + threadIdx.x;
    if (e >= EE) return;
    int s = ei[e], d = ei[EE + e];
    int pos = g_rowptr[d] + g_epos[e];
    const float4* p = (const float4*)(ea + (size_t)e * EDD);
    float4 v0 = p[0], v1 = p[1], v2 = p[2], v3 = p[3];
    float el[LL];
#pragma unroll
    for (int l = 0; l < LL; l++) {
        const float* w = wv + l * EDD;
        el[l] = v0.x * w[0]  + v0.y * w[1]  + v0.z * w[2]  + v0.w * w[3]
              + v1.x * w[4]  + v1.y * w[5]  + v1.z * w[6]  + v1.w * w[7]
              + v2.x * w[8]  + v2.y * w[9]  + v2.z * w[10] + v2.w * w[11]
              + v3.x * w[12] + v3.y * w[13] + v3.z * w[14] + v3.w * w[15];
    }
    __half2 e01 = __floats2half2_rn(el[0], el[1]);
    __half2 e23 = __floats2half2_rn(el[2], el[3]);
    uint4 u;
    u.x = (unsigned)s;
    u.y = *(unsigned*)&e01;
    u.z = *(unsigned*)&e23;
    u.w = 0;
    g_edge[pos] = u;
}

// ---------------- layer-0 gemm: hw0 = x @ W0 (fp16 wmma, fp16 hw out) -------
__global__ void __launch_bounds__(256, 4)
k_gemm0(const float* __restrict__ x,
        const float* __restrict__ W_l,
        const float* __restrict__ as_l,
        const float* __restrict__ ad_l) {
    __shared__ __align__(32) __half shA[64 * 72];
    __shared__ __align__(32) __half shB[64 * 72];
    __shared__ float sout[64 * 72];
    __shared__ float sas[64], sad[64];
    int t = threadIdx.x;
    int row0 = blockIdx.x * 64;
    if (t < 64) { sas[t] = as_l[t]; sad[t] = ad_l[t]; }
    for (int i = t; i < 1024; i += 256) {
        int r = i >> 4, ck = i & 15;
        float4 wv = ((const float4*)W_l)[i];
        *(__half2*)&shB[r * 72 + ck * 4]     = __floats2half2_rn(wv.x, wv.y);
        *(__half2*)&shB[r * 72 + ck * 4 + 2] = __floats2half2_rn(wv.z, wv.w);
        int row = row0 + r;
        float4 v = (row < NN) ? ((const float4*)x)[row * 16 + ck]
                              : make_float4(0.f, 0.f, 0.f, 0.f);
        *(__half2*)&shA[r * 72 + ck * 4]     = __floats2half2_rn(v.x, v.y);
        *(__half2*)&shA[r * 72 + ck * 4 + 2] = __floats2half2_rn(v.z, v.w);
    }
    __syncthreads();

    int w = t >> 5;
    int trow = w >> 2, tcol = w & 3;
    wmma::fragment<wmma::accumulator, 16, 16, 16, float> acc0, acc1;
    wmma::fill_fragment(acc0, 0.f);
    wmma::fill_fragment(acc1, 0.f);
#pragma unroll
    for (int kk = 0; kk < 4; kk++) {
        wmma::fragment<wmma::matrix_a, 16, 16, 16, __half, wmma::row_major> a0, a1;
        wmma::fragment<wmma::matrix_b, 16, 16, 16, __half, wmma::row_major> bf;
        wmma::load_matrix_sync(bf, &shB[kk * 16 * 72 + tcol * 16], 72);
        wmma::load_matrix_sync(a0, &shA[trow * 16 * 72 + kk * 16], 72);
        wmma::load_matrix_sync(a1, &shA[(trow + 2) * 16 * 72 + kk * 16], 72);
        wmma::mma_sync(acc0, a0, bf, acc0);
        wmma::mma_sync(acc1, a1, bf, acc1);
    }
    wmma::store_matrix_sync(&sout[trow * 16 * 72 + tcol * 16], acc0, 72,
                            wmma::mem_row_major);
    wmma::store_matrix_sync(&sout[(trow + 2) * 16 * 72 + tcol * 16], acc1, 72,
                            wmma::mem_row_major);
    __syncthreads();

    int r = t >> 2, q = t & 3;          // cols q*16..q*16+15
    int row = row0 + r;
    float4 v[4];
    float ps = 0.f, pd = 0.f;
#pragma unroll
    for (int i = 0; i < 4; i++) {
        v[i] = *(const float4*)&sout[r * 72 + q * 16 + i * 4];
        int c = q * 16 + i * 4;
        ps += v[i].x * sas[c]     + v[i].y * sas[c + 1]
            + v[i].z * sas[c + 2] + v[i].w * sas[c + 3];
        pd += v[i].x * sad[c]     + v[i].y * sad[c + 1]
            + v[i].z * sad[c + 2] + v[i].w * sad[c + 3];
    }
    ps += __shfl_xor_sync(0xffffffffu, ps, 1);
    ps += __shfl_xor_sync(0xffffffffu, ps, 2);
    pd += __shfl_xor_sync(0xffffffffu, pd, 1);
    pd += __shfl_xor_sync(0xffffffffu, pd, 2);
    if (row < NN) {
        __half2 h0 = __floats2half2_rn(v[0].x, v[0].y);
        __half2 h1 = __floats2half2_rn(v[0].z, v[0].w);
        __half2 h2 = __floats2half2_rn(v[1].x, v[1].y);
        __half2 h3 = __floats2half2_rn(v[1].z, v[1].w);
        __half2 h4 = __floats2half2_rn(v[2].x, v[2].y);
        __half2 h5 = __floats2half2_rn(v[2].z, v[2].w);
        __half2 h6 = __floats2half2_rn(v[3].x, v[3].y);
        __half2 h7 = __floats2half2_rn(v[3].z, v[3].w);
        uint4 u0, u1;
        u0.x = *(unsigned*)&h0; u0.y = *(unsigned*)&h1;
        u0.z = *(unsigned*)&h2; u0.w = *(unsigned*)&h3;
        u1.x = *(unsigned*)&h4; u1.y = *(unsigned*)&h5;
        u1.z = *(unsigned*)&h6; u1.w = *(unsigned*)&h7;
        ((uint4*)g_hwh[0])[row * 8 + q * 2]     = u0;
        ((uint4*)g_hwh[0])[row * 8 + q * 2 + 1] = u1;
        if (q == 0) { g_ssrc2[0][row] = ps; g_sdst2[0][row] = pd; }
    }
}

// ---------------- FUSED: agg(layer l) + gemm(layer l+1) --------------------
__global__ void __launch_bounds__(512, 2)
k_fused(int layer,
        const float* __restrict__ Wn,    // W[l+1]
        const float* __restrict__ asn,   // a_src[l+1]
        const float* __restrict__ adn,   // a_dst[l+1]
        const float* __restrict__ b_l) { // b[l]
    __shared__ __align__(32) __half shA[64 * 72];
    __shared__ __align__(32) __half shB[64 * 72];
    __shared__ float sout[64 * 72];
    __shared__ float sas[64], sad[64];
    __shared__ int rowids[64];
    int rd = layer & 1, wr = (layer + 1) & 1;
    const float* ssrc_in = g_ssrc2[rd];
    const float* sdst_in = g_sdst2[rd];
    const float4* hw_in = (const float4*)g_hwh[rd];   // 8 float4 per row
    int shift = 16 * layer;
    int t = threadIdx.x;
    int w = t >> 5, lane = t & 31;
    int grp = lane >> 3, hl = lane & 7;
    int local = w * 4 + grp;
    int oi = blockIdx.x * 64 + local;
    int n = (oi < NN) ? g_nodeord[oi] : -1;
    if (t < 64) { sas[t] = asn[t]; sad[t] = adn[t]; }
    if (hl == 0) rowids[local] = n;
    for (int i = t; i < 1024; i += 512) {
        int r = i >> 4, ck = i & 15;
        float4 wv = ((const float4*)Wn)[i];
        *(__half2*)&shB[r * 72 + ck * 4]     = __floats2half2_rn(wv.x, wv.y);
        *(__half2*)&shB[r * 72 + ck * 4 + 2] = __floats2half2_rn(wv.z, wv.w);
    }

    // ---- agg phase: lane covers cols 8hl..8hl+7 ----
    if (n >= 0) {
        int s0 = g_rowptr[n], s1 = g_rowptr[n + 1];
        float sd = sdst_in[n];
        unsigned long long acc0 = pk2(0.f, 0.f);
        unsigned long long acc1 = pk2(0.f, 0.f);
        unsigned long long acc2 = pk2(0.f, 0.f);
        unsigned long long acc3 = pk2(0.f, 0.f);
        float denom = 0.f;
#pragma unroll 4
        for (int i = s0; i < s1; i++) {
            uint4 u = g_edge[i];
            int src = (int)u.x;
            unsigned long long pk = ((unsigned long long)u.z << 32) | u.y;
            unsigned short hb = (unsigned short)(pk >> shift);
            float elv = __half2float(__ushort_as_half(hb));
            float sc = ssrc_in[src] + sd + elv;
            sc = fmaxf(sc, 0.2f * sc);           // leaky_relu
            float p = __expf(sc);
            denom += p;
            float4 va = hw_in[src * 8 + hl];     // 128B row, one LDG.128
            const __half2* hp = (const __half2*)&va;
            float2 f0 = __half22float2(hp[0]);
            float2 f1 = __half22float2(hp[1]);
            float2 f2 = __half22float2(hp[2]);
            float2 f3 = __half22float2(hp[3]);
            unsigned long long pp = pk2(p, p);
            acc0 = ffma2(pp, pk2(f0.x, f0.y), acc0);
            acc1 = ffma2(pp, pk2(f1.x, f1.y), acc1);
            acc2 = ffma2(pp, pk2(f2.x, f2.y), acc2);
            acc3 = ffma2(pp, pk2(f3.x, f3.y), acc3);
        }
        float inv = (denom > 0.f) ? (1.f / denom) : 0.f;
        float2 a0 = upk2(acc0), a1 = upk2(acc1), a2 = upk2(acc2), a3 = upk2(acc3);
        float4 ba = ((const float4*)b_l)[2 * hl];
        float4 bb = ((const float4*)b_l)[2 * hl + 1];
        float o0 = fmaxf(a0.x * inv + ba.x, 0.f);
        float o1 = fmaxf(a0.y * inv + ba.y, 0.f);
        float o2 = fmaxf(a1.x * inv + ba.z, 0.f);
        float o3 = fmaxf(a1.y * inv + ba.w, 0.f);
        float o4 = fmaxf(a2.x * inv + bb.x, 0.f);
        float o5 = fmaxf(a2.y * inv + bb.y, 0.f);
        float o6 = fmaxf(a3.x * inv + bb.z, 0.f);
        float o7 = fmaxf(a3.y * inv + bb.w, 0.f);
        *(__half2*)&shA[local * 72 + 8 * hl]     = __floats2half2_rn(o0, o1);
        *(__half2*)&shA[local * 72 + 8 * hl + 2] = __floats2half2_rn(o2, o3);
        *(__half2*)&shA[local * 72 + 8 * hl + 4] = __floats2half2_rn(o4, o5);
        *(__half2*)&shA[local * 72 + 8 * hl + 6] = __floats2half2_rn(o6, o7);
    } else {
        __half2 z = __floats2half2_rn(0.f, 0.f);
        *(__half2*)&shA[local * 72 + 8 * hl]     = z;
        *(__half2*)&shA[local * 72 + 8 * hl + 2] = z;
        *(__half2*)&shA[local * 72 + 8 * hl + 4] = z;
        *(__half2*)&shA[local * 72 + 8 * hl + 6] = z;
    }
    __syncthreads();

    // ---- gemm phase ----
    {
        int trow = w >> 2, tcol = w & 3;
        wmma::fragment<wmma::accumulator, 16, 16, 16, float> acc;
        wmma::fill_fragment(acc, 0.f);
#pragma unroll
        for (int kk = 0; kk < 4; kk++) {
            wmma::fragment<wmma::matrix_a, 16, 16, 16, __half, wmma::row_major> af;
            wmma::fragment<wmma::matrix_b, 16, 16, 16, __half, wmma::row_major> bf;
            wmma::load_matrix_sync(af, &shA[trow * 16 * 72 + kk * 16], 72);
            wmma::load_matrix_sync(bf, &shB[kk * 16 * 72 + tcol * 16], 72);
            wmma::mma_sync(acc, af, bf, acc);
        }
        wmma::store_matrix_sync(&sout[trow * 16 * 72 + tcol * 16], acc, 72,
                                wmma::mem_row_major);
    }
    __syncthreads();

    // ---- epilogue ----
    int r = t >> 3, q = t & 7;
    float4 v0 = *(const float4*)&sout[r * 72 + q * 8];
    float4 v1 = *(const float4*)&sout[r * 72 + q * 8 + 4];
    int c = q * 8;
    float ps = v0.x * sas[c]     + v0.y * sas[c + 1]
             + v0.z * sas[c + 2] + v0.w * sas[c + 3]
             + v1.x * sas[c + 4] + v1.y * sas[c + 5]
             + v1.z * sas[c + 6] + v1.w * sas[c + 7];
    float pd = v0.x * sad[c]     + v0.y * sad[c + 1]
             + v0.z * sad[c + 2] + v0.w * sad[c + 3]
             + v1.x * sad[c + 4] + v1.y * sad[c + 5]
             + v1.z * sad[c + 6] + v1.w * sad[c + 7];
    ps += __shfl_xor_sync(0xffffffffu, ps, 1);
    ps += __shfl_xor_sync(0xffffffffu, ps, 2);
    ps += __shfl_xor_sync(0xffffffffu, ps, 4);
    pd += __shfl_xor_sync(0xffffffffu, pd, 1);
    pd += __shfl_xor_sync(0xffffffffu, pd, 2);
    pd += __shfl_xor_sync(0xffffffffu, pd, 4);
    int rowg = rowids[r];
    if (rowg >= 0) {
        __half2 h0 = __floats2half2_rn(v0.x, v0.y);
        __half2 h1 = __floats2half2_rn(v0.z, v0.w);
        __half2 h2 = __floats2half2_rn(v1.x, v1.y);
        __half2 h3 = __floats2half2_rn(v1.z, v1.w);
        uint4 u;
        u.x = *(unsigned*)&h0; u.y = *(unsigned*)&h1;
        u.z = *(unsigned*)&h2; u.w = *(unsigned*)&h3;
        ((uint4*)g_hwh[wr])[rowg * 8 + q] = u;
        if (q == 0) { g_ssrc2[wr][rowg] = ps; g_sdst2[wr][rowg] = pd; }
    }
}

// ---------------- final-layer aggregation (layer 3, reads parity 1) --------
__global__ void k_agg_last(const float* __restrict__ b_l) {
    int warp = (blockIdx.x * blockDim.x + threadIdx.x) >> 5;
    int lane = threadIdx.x & 31;
    int grp = lane >> 3, hl = lane & 7;
    int oi = warp * 4 + grp;
    if (oi >= NN) return;
    int n = g_nodeord[oi];
    int s0 = g_rowptr[n], s1 = g_rowptr[n + 1];
    float sd = g_sdst2[1][n];
    const float4* hw_in = (const float4*)g_hwh[1];
    unsigned long long acc0 = pk2(0.f, 0.f);
    unsigned long long acc1 = pk2(0.f, 0.f);
    unsigned long long acc2 = pk2(0.f, 0.f);
    unsigned long long acc3 = pk2(0.f, 0.f);
    float denom = 0.f;
#pragma unroll 4
    for (int i = s0; i < s1; i++) {
        uint4 u = g_edge[i];
        int src = (int)u.x;
        float elv = __half2float(__ushort_as_half((unsigned short)(u.z >> 16)));
        float sc = g_ssrc2[1][src] + sd + elv;
        sc = fmaxf(sc, 0.2f * sc);
        float p = __expf(sc);
        denom += p;
        float4 va = hw_in[src * 8 + hl];
        const __half2* hp = (const __half2*)&va;
        float2 f0 = __half22float2(hp[0]);
        float2 f1 = __half22float2(hp[1]);
        float2 f2 = __half22float2(hp[2]);
        float2 f3 = __half22float2(hp[3]);
        unsigned long long pp = pk2(p, p);
        acc0 = ffma2(pp, pk2(f0.x, f0.y), acc0);
        acc1 = ffma2(pp, pk2(f1.x, f1.y), acc1);
        acc2 = ffma2(pp, pk2(f2.x, f2.y), acc2);
        acc3 = ffma2(pp, pk2(f3.x, f3.y), acc3);
    }
    float inv = (denom > 0.f) ? (1.f / denom) : 0.f;
    float2 a0 = upk2(acc0), a1 = upk2(acc1), a2 = upk2(acc2), a3 = upk2(acc3);
    float4 ba = ((const float4*)b_l)[2 * hl];
    float4 bb = ((const float4*)b_l)[2 * hl + 1];
    float4 oa = make_float4(a0.x * inv + ba.x, a0.y * inv + ba.y,
                            a1.x * inv + ba.z, a1.y * inv + ba.w);
    float4 ob = make_float4(a2.x * inv + bb.x, a2.y * inv + bb.y,
                            a3.x * inv + bb.z, a3.y * inv + bb.w);
    float4* hout = (float4*)g_hbuf;
    hout[n * 16 + 2 * hl] = oa;
    hout[n * 16 + 2 * hl + 1] = ob;
}

// ---------------- global mean pool (block per group) ------------------------
__global__ void k_pool() {
    const float* h = g_hbuf;
    int g = blockIdx.x;
    int t = threadIdx.x;
    int col = t & 63, rs = t >> 6;
    int s0 = g_gstart[g], s1 = g_gstart[g + 1];
    float acc = 0.f;
    for (int n = s0 + rs; n < s1; n += 4) acc += h[n * DD + col];
    __shared__ float sh[256];
    sh[t] = acc;
    __syncthreads();
    if (rs == 0) {
        float v = sh[col] + sh[64 + col] + sh[128 + col] + sh[192 + col];
        float cnt = (float)(s1 - s0);
        g_pooled[g * DD + col] = v / fmaxf(cnt, 1.f);
    }
}

// ---------------- FC: out[g, 2k2..2k2+1] = pooled[g] . Wfc + bfc -----------
__global__ void k_fc(const float* __restrict__ Wfc,
                     const float* __restrict__ bfc,
                     float* __restrict__ out) {
    int g = blockIdx.y;
    int k2 = blockIdx.x * 256 + threadIdx.x;   // pair index 0..1023
    __shared__ float sp[DD];
    if (threadIdx.x < DD) sp[threadIdx.x] = g_pooled[g * DD + threadIdx.x];
    __syncthreads();
    const float2* W2 = (const float2*)Wfc;
    float2 bb = ((const float2*)bfc)[k2];
    unsigned long long acc = pk2(bb.x, bb.y);
#pragma unroll
    for (int d = 0; d < DD; d++) {
        float2 w = __ldg(&W2[d * 1024 + k2]);
        acc = ffma2(pk2(sp[d], sp[d]), pk2(w.x, w.y), acc);
    }
    ((float2*)out)[g * 1024 + k2] = upk2(acc);
}

// ---------------- launch -----------------------------------------------------
// Graph-forked: CSR build starts at t=0 on s2; main stream runs prep + gemm0
// concurrently. Scatter waits on prep (needs g_wev).
extern "C" void kernel_launch(void* const* d_in, const int* in_sizes, int n_in,
                              void* d_out, int out_size) {
    const float* x     = (const float*)d_in[0];
    const int*   ei    = (const int*)  d_in[1];
    const float* ea    = (const float*)d_in[2];
    const int*   batch = (const int*)  d_in[3];
    const float* W     = (const float*)d_in[4];
    const float* a_src = (const float*)d_in[5];
    const float* a_dst = (const float*)d_in[6];
    const float* We    = (const float*)d_in[7];
    const float* a_e   = (const float*)d_in[8];
    const float* b     = (const float*)d_in[9];
    const float* Wfc   = (const float*)d_in[10];
    const float* bfc   = (const float*)d_in[11];
    float* out = (float*)d_out;

    cudaStream_t s2;
    cudaStreamCreateWithFlags(&s2, cudaStreamNonBlocking);
    cudaEvent_t evFork, evPrep, evJoin;
    cudaEventCreateWithFlags(&evFork, cudaEventDisableTiming);
    cudaEventCreateWithFlags(&evPrep, cudaEventDisableTiming);
    cudaEventCreateWithFlags(&evJoin, cudaEventDisableTiming);

    // fork at t=0: CSR chain on s2, prep+gemm0 on main
    cudaEventRecord(evFork, 0);
    cudaStreamWaitEvent(s2, evFork, 0);
    k_count<<<(EE + 255) / 256, 256, 0, s2>>>(ei);
    k_scanA<<<NB, 256, 0, s2>>>();
    k_scanC<<<NB, 256, 0, s2>>>();
    k_degorder<<<NB, 256, 0, s2>>>();

    k_prep<<<(NN + 255) / 256, 256>>>(We, a_e, batch);
    cudaEventRecord(evPrep, 0);
    k_gemm0<<<(NN + 63) / 64, 256>>>(x, W, a_src, a_dst);

    cudaStreamWaitEvent(s2, evPrep, 0);   // scatter needs g_wev
    k_scatter<<<(EE + 255) / 256, 256, 0, s2>>>(ei, ea);
    cudaEventRecord(evJoin, s2);

    cudaStreamWaitEvent(0, evJoin, 0);

    // fused agg(l) + gemm(l+1), l = 0..2
    for (int l = 0; l < LL - 1; l++) {
        k_fused<<<(NN + 63) / 64, 512>>>(l, W + (l + 1) * DD * DD,
                                         a_src + (l + 1) * DD,
                                         a_dst + (l + 1) * DD,
                                         b + l * DD);
    }
    // final aggregation (layer 3)
    k_agg_last<<<(NN * 8 + 255) / 256, 256>>>(b + 3 * DD);

    k_pool<<<GG, 256>>>();
    dim3 fcg(1024 / 256, GG);
    k_fc<<<fcg, 256>>>(Wfc, bfc, out);
}